// round 15
// baseline (speedup 1.0000x reference)
#include <cuda_runtime.h>
#include <cuda_bf16.h>
#include <cstdint>

#define M_B 4096
#define N_H 16384
#define K_D 1024
#define KSEL 32
#define NCHUNKS 512          // 16384 / 32 cols per chunk
#define CANDCAP 512
#define TCHUNKS 4
#define T_CH (M_B / TCHUNKS)

// ---------------- scratch (device globals; no allocation) ----------------
__device__ __nv_bfloat16 g_xb[(size_t)M_B * K_D];        // 8MB   x in bf16
__device__ __nv_bfloat16 g_wb[(size_t)N_H * K_D];        // 33MB  W_enc in bf16
__device__ __nv_bfloat16 g_encbf[(size_t)M_B * N_H];     // 134MB approx enc (bf16)
__device__ unsigned short g_cmax[(size_t)M_B * NCHUNKS]; // 4MB chunk max |bf16| keys
__device__ float g_Wt[(size_t)N_H * K_D];                // 64MB  W_dec^T
__device__ int   g_cand[(size_t)M_B * CANDCAP];          // 8MB candidate indices
__device__ float g_cval[(size_t)M_B * CANDCAP];          // 8MB candidate exact values
__device__ int   g_ccnt[M_B];
__device__ float g_thr[M_B];

// ======================= helpers =======================
__device__ __forceinline__ uint32_t smem_u32(const void* p) {
    uint32_t a;
    asm("{ .reg .u64 t; cvta.to.shared.u64 t, %1; cvt.u32.u64 %0, t; }" : "=r"(a) : "l"(p));
    return a;
}
__device__ __forceinline__ void cp16(uint32_t dst, const void* src) {
    asm volatile("cp.async.cg.shared.global [%0], [%1], 16;" :: "r"(dst), "l"(src) : "memory");
}
__device__ __forceinline__ void cp_commit() {
    asm volatile("cp.async.commit_group;" ::: "memory");
}
template <int N> __device__ __forceinline__ void cp_wait() {
    asm volatile("cp.async.wait_group %0;" :: "n"(N) : "memory");
}
__device__ __forceinline__ void ldsm4(uint32_t& r0, uint32_t& r1, uint32_t& r2,
                                      uint32_t& r3, uint32_t a) {
    asm volatile("ldmatrix.sync.aligned.m8n8.x4.shared.b16 {%0,%1,%2,%3}, [%4];"
                 : "=r"(r0), "=r"(r1), "=r"(r2), "=r"(r3) : "r"(a));
}
__device__ __forceinline__ void mma16816(float* d, uint32_t a0, uint32_t a1,
                                         uint32_t a2, uint32_t a3,
                                         uint32_t b0, uint32_t b1) {
    asm volatile("mma.sync.aligned.m16n8k16.row.col.f32.bf16.bf16.f32 "
                 "{%0,%1,%2,%3}, {%4,%5,%6,%7}, {%8,%9}, {%0,%1,%2,%3};"
                 : "+f"(d[0]), "+f"(d[1]), "+f"(d[2]), "+f"(d[3])
                 : "r"(a0), "r"(a1), "r"(a2), "r"(a3), "r"(b0), "r"(b1));
}
#define SWZ(off) ((off) ^ (((off) >> 3) & 0x70))

// ======================================================================
// fp32 -> bf16 conversion
// ======================================================================
__global__ __launch_bounds__(256) void convert_kernel(const float* __restrict__ src,
                                                      __nv_bfloat16* __restrict__ dst) {
    const size_t g = (size_t)blockIdx.x * 256 + threadIdx.x;
    const float4 v = ((const float4*)src)[g];
    __nv_bfloat162 lo = __floats2bfloat162_rn(v.x, v.y);
    __nv_bfloat162 hi = __floats2bfloat162_rn(v.z, v.w);
    uint32_t a = *(uint32_t*)&lo, b = *(uint32_t*)&hi;
    ((uint2*)dst)[g] = make_uint2(a, b);
}

// ======================================================================
// Zero the sparse output region (standalone, side stream)
// ======================================================================
__global__ __launch_bounds__(256) void zero_kernel(float4* __restrict__ p, size_t n4) {
    const size_t stride = (size_t)gridDim.x * 256;
    const float4 z = make_float4(0.f, 0.f, 0.f, 0.f);
    for (size_t i = (size_t)blockIdx.x * 256 + threadIdx.x; i < n4; i += stride)
        p[i] = z;
}

// ======================================================================
// Approx encoder GEMM (bf16 HMMA) — R5/R8-proven config, verbatim.
// ======================================================================
__global__ __launch_bounds__(256) void enc_hmma_kernel(const float* __restrict__ bias,
                                                       __nv_bfloat16* __restrict__ C) {
    extern __shared__ __align__(1024) char smem[];   // 2 stages x 32KB
    const int tid = threadIdx.x;
    const int wid = tid >> 5, lane = tid & 31;
    const int bm = blockIdx.y * 128, bn = blockIdx.x * 128;
    const int wm = (wid >> 2) * 64, wn = (wid & 3) * 32;

    float acc[4][4][4];
#pragma unroll
    for (int i = 0; i < 4; i++)
#pragma unroll
        for (int j = 0; j < 4; j++)
#pragma unroll
            for (int q = 0; q < 4; q++) acc[i][j][q] = 0.f;

    const __nv_bfloat16* Abase = g_xb + (size_t)bm * K_D;
    const __nv_bfloat16* Bbase = g_wb + (size_t)bn * K_D;
    auto base_of = [&](int s) { return smem_u32(smem) + s * 32768; };

#define LOAD_TILE(s, kt)                                                          \
    {                                                                             \
        const uint32_t sa = base_of(s);                                           \
        const __nv_bfloat16* Ag = Abase + (kt) * 64;                              \
        const __nv_bfloat16* Bg = Bbase + (kt) * 64;                              \
        _Pragma("unroll")                                                         \
        for (int i = 0; i < 4; i++) {                                             \
            int u = tid + i * 256, row = u >> 3, kb = u & 7;                      \
            cp16(sa + SWZ(row * 128 + kb * 16), Ag + (size_t)row * K_D + kb * 8); \
        }                                                                         \
        _Pragma("unroll")                                                         \
        for (int i = 0; i < 4; i++) {                                             \
            int u = tid + i * 256, row = u >> 3, kb = u & 7;                      \
            cp16(sa + 16384 + SWZ(row * 128 + kb * 16), Bg + (size_t)row * K_D + kb * 8); \
        }                                                                         \
        cp_commit();                                                              \
    }

    LOAD_TILE(0, 0);
    int buf = 0;
    for (int kt = 0; kt < K_D / 64; ++kt) {
        if (kt + 1 < K_D / 64) { LOAD_TILE(buf ^ 1, kt + 1); cp_wait<1>(); }
        else cp_wait<0>();
        __syncthreads();

        const uint32_t sa = base_of(buf);
        const uint32_t sb = sa + 16384;
#pragma unroll
        for (int ks = 0; ks < 4; ks++) {
            uint32_t ra[4][4], rb[2][4];
#pragma unroll
            for (int mi = 0; mi < 4; mi++) {
                const int row = wm + mi * 16 + (lane & 15);
                const int koff = ks * 32 + ((lane >> 4) << 4);
                ldsm4(ra[mi][0], ra[mi][1], ra[mi][2], ra[mi][3],
                      sa + SWZ(row * 128 + koff));
            }
#pragma unroll
            for (int nb = 0; nb < 2; nb++) {
                const int nrow = wn + nb * 16 + ((lane >> 4) << 3) + (lane & 7);
                const int koff = ks * 32 + (((lane >> 3) & 1) << 4);
                ldsm4(rb[nb][0], rb[nb][1], rb[nb][2], rb[nb][3],
                      sb + SWZ(nrow * 128 + koff));
            }
#pragma unroll
            for (int mi = 0; mi < 4; mi++)
#pragma unroll
                for (int nj = 0; nj < 4; nj++)
                    mma16816(acc[mi][nj], ra[mi][0], ra[mi][1], ra[mi][2], ra[mi][3],
                             rb[nj >> 1][(nj & 1) * 2], rb[nj >> 1][(nj & 1) * 2 + 1]);
        }
        __syncthreads();
        buf ^= 1;
    }

    // epilogue: + bias -> bf16 store; per-(row, 32-col-chunk) max keys
    const int g = lane >> 2, t = lane & 3;
    const int chunk = (bn >> 5) + (wid & 3);
#pragma unroll
    for (int mi = 0; mi < 4; mi++) {
        const int r0 = bm + wm + mi * 16 + g;
        unsigned k0 = 0u, k1 = 0u;
#pragma unroll
        for (int nj = 0; nj < 4; nj++) {
            const int col = bn + wn + nj * 8 + 2 * t;
            const float2 bv = *(const float2*)(bias + col);
            __nv_bfloat162 p0 = __floats2bfloat162_rn(acc[mi][nj][0] + bv.x,
                                                      acc[mi][nj][1] + bv.y);
            __nv_bfloat162 p1 = __floats2bfloat162_rn(acc[mi][nj][2] + bv.x,
                                                      acc[mi][nj][3] + bv.y);
            const uint32_t u0 = *(uint32_t*)&p0, u1 = *(uint32_t*)&p1;
            k0 = max(k0, max(u0 & 0x7FFFu, (u0 >> 16) & 0x7FFFu));
            k1 = max(k1, max(u1 & 0x7FFFu, (u1 >> 16) & 0x7FFFu));
            *(__nv_bfloat162*)(C + (size_t)r0 * N_H + col) = p0;
            *(__nv_bfloat162*)(C + (size_t)(r0 + 8) * N_H + col) = p1;
        }
        k0 = max(k0, __shfl_xor_sync(0xffffffffu, k0, 1));
        k0 = max(k0, __shfl_xor_sync(0xffffffffu, k0, 2));
        k1 = max(k1, __shfl_xor_sync(0xffffffffu, k1, 1));
        k1 = max(k1, __shfl_xor_sync(0xffffffffu, k1, 2));
        if (t == 0) {
            g_cmax[(size_t)r0 * NCHUNKS + chunk] = (unsigned short)k0;
            g_cmax[(size_t)(r0 + 8) * NCHUNKS + chunk] = (unsigned short)k1;
        }
    }
}

// ======================================================================
// Transpose W_dec [1024, 16384] -> g_Wt [16384, 1024]
// ======================================================================
__global__ void transpose_kernel(const float* __restrict__ W) {
    __shared__ float t[32][33];
    const int h0 = blockIdx.x * 32;
    const int d0 = blockIdx.y * 32;
    const int tx = threadIdx.x, ty = threadIdx.y;
#pragma unroll
    for (int i = 0; i < 32; i += 8)
        t[ty + i][tx] = W[(size_t)(d0 + ty + i) * N_H + h0 + tx];
    __syncthreads();
#pragma unroll
    for (int i = 0; i < 32; i += 8)
        g_Wt[(size_t)(h0 + ty + i) * K_D + d0 + tx] = t[tx][ty + i];
}

// ======================================================================
// S1: per-row threshold + candidate emission (light, latency-bound).
// ======================================================================
__global__ __launch_bounds__(256) void select1_kernel(int row_base) {
    __shared__ unsigned short scmax[NCHUNKS];    // 1KB
    __shared__ unsigned short achunk[NCHUNKS];   // 1KB
    __shared__ unsigned s_na, s_emit, s_thrkey;

    const int tid = threadIdx.x;
    const int row = row_base + blockIdx.x;
    const int wid = tid >> 5, lane = tid & 31;

    if (tid == 0) { s_na = 0u; s_emit = 0u; }
    ((uint32_t*)scmax)[tid] = ((const uint32_t*)(g_cmax + (size_t)row * NCHUNKS))[tid];
    __syncthreads();

    if (wid == 0) {
        const uint32_t* sc32 = (const uint32_t*)scmax;
        unsigned mx = 0u;
        for (int i = 0; i < 8; i++) {
            const uint32_t u = sc32[lane + 32 * i];
            mx = max(mx, max(u & 0xFFFFu, u >> 16));
        }
#pragma unroll
        for (int o = 16; o; o >>= 1) mx = max(mx, __shfl_xor_sync(0xffffffffu, mx, o));
        unsigned lo = 0u, hi = mx;
        for (int it = 0; it < 15; ++it) {
            if (lo >= hi) break;
            const unsigned mid = lo + ((hi - lo + 1) >> 1);
            unsigned c = 0;
            for (int i = 0; i < 8; i++) {
                const uint32_t u = sc32[lane + 32 * i];
                c += ((u & 0xFFFFu) >= mid) + ((u >> 16) >= mid);
            }
#pragma unroll
            for (int o = 16; o; o >>= 1) c += __shfl_xor_sync(0xffffffffu, c, o);
            if (c >= (unsigned)KSEL) lo = mid; else hi = mid - 1;
        }
        const unsigned short tsub = (unsigned short)lo;
        float tsubf;
        { __nv_bfloat16 h = *(__nv_bfloat16*)&tsub; tsubf = __bfloat162float(h); }
        const float thrf = fmaxf(tsubf - (0.03125f + 0.015625f * tsubf), 0.f);
        unsigned thrkey;
        { __nv_bfloat16 h = __float2bfloat16_rz(thrf); thrkey = *(unsigned short*)&h; }
        if (lane == 0) { s_thrkey = thrkey; g_thr[row] = thrf; }
        for (int i = 0; i < 8; i++) {
            const uint32_t u = sc32[lane + 32 * i];
            if ((u & 0xFFFFu) >= thrkey) {
                unsigned p = atomicAdd(&s_na, 1u);
                achunk[p] = (unsigned short)(2 * (lane + 32 * i));
            }
            if ((u >> 16) >= thrkey) {
                unsigned p = atomicAdd(&s_na, 1u);
                achunk[p] = (unsigned short)(2 * (lane + 32 * i) + 1);
            }
        }
    }
    __syncthreads();
    const unsigned thrkey = s_thrkey;
    const int na = (int)s_na;

    const uint32_t* erow = (const uint32_t*)(g_encbf + (size_t)row * N_H);
    for (int i = wid * 2; i < na; i += 16) {
        const int slot = i + (lane >> 4);
        if (slot < na) {
            const int c = achunk[slot];
            const uint32_t u = erow[c * 16 + (lane & 15)];
            const unsigned klo = u & 0x7FFFu, khi = (u >> 16) & 0x7FFFu;
            if (klo >= thrkey) {
                unsigned p = atomicAdd(&s_emit, 1u);
                if (p < CANDCAP) g_cand[(size_t)row * CANDCAP + p] = c * 32 + 2 * (lane & 15);
            }
            if (khi >= thrkey) {
                unsigned p = atomicAdd(&s_emit, 1u);
                if (p < CANDCAP) g_cand[(size_t)row * CANDCAP + p] = c * 32 + 2 * (lane & 15) + 1;
            }
        }
    }
    __syncthreads();
    if (tid == 0) g_ccnt[row] = (int)min(s_emit, (unsigned)CANDCAP);
}

// ======================================================================
// S2: exact fp32 recompute of all candidates (throughput-bound).
// ======================================================================
__global__ __launch_bounds__(256) void recompute_kernel(const float* __restrict__ x,
                                                        const float* __restrict__ W,
                                                        const float* __restrict__ benc,
                                                        int row_base) {
    __shared__ float sx[K_D];
    const int tid = threadIdx.x;
    const int row = row_base + blockIdx.x;
    const int wid = tid >> 5, lane = tid & 31;

    ((float4*)sx)[tid] = ((const float4*)(x + (size_t)row * K_D))[tid];
    __syncthreads();

    const int cn = g_ccnt[row];
    const float4* sx4 = (const float4*)sx;
    for (int c = wid; c < cn; c += 8) {
        const int j = g_cand[(size_t)row * CANDCAP + c];
        const float4* wr = (const float4*)(W + (size_t)j * K_D);
        float s = 0.f;
#pragma unroll
        for (int i = 0; i < 8; i++) {
            const float4 w4 = wr[lane + i * 32];
            const float4 x4 = sx4[lane + i * 32];
            s += w4.x * x4.x + w4.y * x4.y + w4.z * x4.z + w4.w * x4.w;
        }
#pragma unroll
        for (int o = 16; o; o >>= 1) s += __shfl_xor_sync(0xffffffffu, s, o);
        if (lane == 0) g_cval[(size_t)row * CANDCAP + c] = s + benc[j];
    }
}

// ======================================================================
// D3 (merged S3+decode): exact top-32 bisection among candidates +
// scatter into pre-zeroed sparse row + decode the row from g_Wt.
// Working set here is g_Wt only (no W_enc) -> no L2 thrash.
// ======================================================================
__global__ __launch_bounds__(256) void decode3_kernel(const float* __restrict__ bdec,
                                                      float* __restrict__ sparse,
                                                      float* __restrict__ decoded) {
    __shared__ float cval[CANDCAP];
    __shared__ int   cidx[CANDCAP];
    __shared__ int   s_sidx[KSEL];
    __shared__ float s_sval[KSEL];
    __shared__ unsigned s_sel;

    const int tid = threadIdx.x;
    const int row = blockIdx.x;
    const int wid = tid >> 5, lane = tid & 31;
    const int cn = g_ccnt[row];

    if (tid == 0) s_sel = 0u;
    if (tid < KSEL) { s_sidx[tid] = 0; s_sval[tid] = 0.f; }
    for (int i = tid; i < cn; i += 256) {
        cval[i] = g_cval[(size_t)row * CANDCAP + i];
        cidx[i] = g_cand[(size_t)row * CANDCAP + i];
    }
    __syncthreads();

    if (wid == 0) {
        unsigned mx = 0u;
        for (int i = lane; i < cn; i += 32)
            mx = max(mx, __float_as_uint(fabsf(cval[i])));
#pragma unroll
        for (int o = 16; o; o >>= 1) mx = max(mx, __shfl_xor_sync(0xffffffffu, mx, o));
        unsigned lo = __float_as_uint(g_thr[row]), hi = mx;
        for (int it = 0; it < 32; ++it) {
            if (lo >= hi) break;
            const unsigned mid = lo + ((hi - lo + 1) >> 1);
            unsigned c = 0;
            for (int i = lane; i < cn; i += 32)
                c += (__float_as_uint(fabsf(cval[i])) >= mid);
#pragma unroll
            for (int o = 16; o; o >>= 1) c += __shfl_xor_sync(0xffffffffu, c, o);
            if (c >= (unsigned)KSEL) lo = mid; else hi = mid - 1;
        }
        const unsigned T = lo;
        for (int i = lane; i < cn; i += 32) {
            const float vv = cval[i];
            if (__float_as_uint(fabsf(vv)) >= T) {
                unsigned p = atomicAdd(&s_sel, 1u);
                if (p < (unsigned)KSEL) { s_sidx[p] = cidx[i]; s_sval[p] = vv; }
            }
        }
    }
    __syncthreads();

    // scatter winners (row pre-zeroed by zero_kernel)
    if (tid < KSEL && tid < (int)min(s_sel, (unsigned)KSEL))
        sparse[(size_t)row * N_H + s_sidx[tid]] = s_sval[tid];

    // decode row
    {
        const float4* Wt4 = (const float4*)g_Wt;
        float4 acc = ((const float4*)bdec)[tid];
#pragma unroll 8
        for (int j = 0; j < KSEL; j++) {
            const float4 w = Wt4[(size_t)s_sidx[j] * (K_D / 4) + tid];
            const float s = s_sval[j];
            acc.x += s * w.x; acc.y += s * w.y; acc.z += s * w.z; acc.w += s * w.w;
        }
        ((float4*)(decoded + (size_t)row * K_D))[tid] = acc;
    }
}

// ======================================================================
extern "C" void kernel_launch(void* const* d_in, const int* in_sizes, int n_in,
                              void* d_out, int out_size) {
    const float* x     = (const float*)d_in[0];
    const float* W_enc = (const float*)d_in[1];
    const float* b_enc = (const float*)d_in[2];
    const float* W_dec = (const float*)d_in[3];
    const float* b_dec = (const float*)d_in[4];

    float* out = (float*)d_out;
    float* sparse  = out;
    float* decoded = out + (size_t)M_B * N_H;

    __nv_bfloat16 *xb = nullptr, *wb = nullptr, *encbf = nullptr;
    cudaGetSymbolAddress((void**)&xb, g_xb);
    cudaGetSymbolAddress((void**)&wb, g_wb);
    cudaGetSymbolAddress((void**)&encbf, g_encbf);

    // one-time host-side handles (created on the uncaptured correctness call)
    static cudaStream_t s_side = nullptr;
    static cudaEvent_t  s_ev0 = nullptr, s_evg = nullptr;
    static cudaEvent_t  s_evs1[TCHUNKS];
    if (s_side == nullptr) {
        cudaStreamCreateWithFlags(&s_side, cudaStreamNonBlocking);
        cudaEventCreateWithFlags(&s_ev0, cudaEventDisableTiming);
        cudaEventCreateWithFlags(&s_evg, cudaEventDisableTiming);
        for (int i = 0; i < TCHUNKS; i++)
            cudaEventCreateWithFlags(&s_evs1[i], cudaEventDisableTiming);
        cudaFuncSetAttribute(enc_hmma_kernel,
                             cudaFuncAttributeMaxDynamicSharedMemorySize, 65536);
    }

    // fork side stream from the (captured) origin stream
    cudaEventRecord(s_ev0, 0);
    cudaStreamWaitEvent(s_side, s_ev0, 0);

    // side stream: W_dec transpose + zero-fill (DRAM-bound; hidden under GEMM)
    transpose_kernel<<<dim3(N_H / 32, K_D / 32), dim3(32, 8), 0, s_side>>>(W_dec);
    zero_kernel<<<8192, 256, 0, s_side>>>((float4*)sparse, (size_t)M_B * N_H / 4);

    // main stream: bf16 conversions -> approx GEMM
    convert_kernel<<<(M_B * K_D / 4) / 256, 256>>>(x, xb);
    convert_kernel<<<(int)(((size_t)N_H * K_D / 4) / 256), 256>>>(W_enc, wb);
    enc_hmma_kernel<<<dim3(N_H / 128, M_B / 128), 256, 65536>>>(b_enc, encbf);
    cudaEventRecord(s_evg, 0);

    // pipelined tail: S1 chunks on side stream, S2 chunks chase on main
    cudaStreamWaitEvent(s_side, s_evg, 0);
    for (int c = 0; c < TCHUNKS; c++) {
        select1_kernel<<<T_CH, 256, 0, s_side>>>(c * T_CH);
        cudaEventRecord(s_evs1[c], s_side);
        cudaStreamWaitEvent(0, s_evs1[c], 0);
        recompute_kernel<<<T_CH, 256>>>(x, W_enc, b_enc, c * T_CH);
    }

    // merged top-32 + scatter + decode (g_Wt phase; zero done long before)
    decode3_kernel<<<M_B, 256>>>(b_dec, sparse, decoded);
}

// round 16
// speedup vs baseline: 1.0236x; 1.0236x over previous
#include <cuda_runtime.h>
#include <cuda_bf16.h>
#include <cstdint>

#define M_B 4096
#define N_H 16384
#define K_D 1024
#define KSEL 32
#define NCHUNKS 512          // 16384 / 32 cols per chunk
#define CANDCAP 512

// ---------------- scratch (device globals; no allocation) ----------------
__device__ __nv_bfloat16 g_xb[(size_t)M_B * K_D];        // 8MB   x in bf16
__device__ __nv_bfloat16 g_wb[(size_t)N_H * K_D];        // 33MB  W_enc in bf16
__device__ __nv_bfloat16 g_encbf[(size_t)M_B * N_H];     // 134MB approx enc (bf16)
__device__ unsigned short g_cmax[(size_t)M_B * NCHUNKS]; // 4MB chunk max |bf16| keys
__device__ float g_Wt[(size_t)N_H * K_D];                // 64MB  W_dec^T
__device__ int   g_cand[(size_t)M_B * CANDCAP];          // 8MB candidate indices
__device__ float g_cval[(size_t)M_B * CANDCAP];          // 8MB candidate exact values
__device__ int   g_ccnt[M_B];
__device__ float g_thr[M_B];

// ======================= helpers =======================
__device__ __forceinline__ uint32_t smem_u32(const void* p) {
    uint32_t a;
    asm("{ .reg .u64 t; cvta.to.shared.u64 t, %1; cvt.u32.u64 %0, t; }" : "=r"(a) : "l"(p));
    return a;
}
__device__ __forceinline__ void cp16(uint32_t dst, const void* src) {
    asm volatile("cp.async.cg.shared.global [%0], [%1], 16;" :: "r"(dst), "l"(src) : "memory");
}
__device__ __forceinline__ void cp_commit() {
    asm volatile("cp.async.commit_group;" ::: "memory");
}
template <int N> __device__ __forceinline__ void cp_wait() {
    asm volatile("cp.async.wait_group %0;" :: "n"(N) : "memory");
}
__device__ __forceinline__ void ldsm4(uint32_t& r0, uint32_t& r1, uint32_t& r2,
                                      uint32_t& r3, uint32_t a) {
    asm volatile("ldmatrix.sync.aligned.m8n8.x4.shared.b16 {%0,%1,%2,%3}, [%4];"
                 : "=r"(r0), "=r"(r1), "=r"(r2), "=r"(r3) : "r"(a));
}
__device__ __forceinline__ void mma16816(float* d, uint32_t a0, uint32_t a1,
                                         uint32_t a2, uint32_t a3,
                                         uint32_t b0, uint32_t b1) {
    asm volatile("mma.sync.aligned.m16n8k16.row.col.f32.bf16.bf16.f32 "
                 "{%0,%1,%2,%3}, {%4,%5,%6,%7}, {%8,%9}, {%0,%1,%2,%3};"
                 : "+f"(d[0]), "+f"(d[1]), "+f"(d[2]), "+f"(d[3])
                 : "r"(a0), "r"(a1), "r"(a2), "r"(a3), "r"(b0), "r"(b1));
}
#define SWZ(off) ((off) ^ (((off) >> 3) & 0x70))

// ======================================================================
// fp32 -> bf16 conversion
// ======================================================================
__global__ __launch_bounds__(256) void convert_kernel(const float* __restrict__ src,
                                                      __nv_bfloat16* __restrict__ dst) {
    const size_t g = (size_t)blockIdx.x * 256 + threadIdx.x;
    const float4 v = ((const float4*)src)[g];
    __nv_bfloat162 lo = __floats2bfloat162_rn(v.x, v.y);
    __nv_bfloat162 hi = __floats2bfloat162_rn(v.z, v.w);
    uint32_t a = *(uint32_t*)&lo, b = *(uint32_t*)&hi;
    ((uint2*)dst)[g] = make_uint2(a, b);
}

// ======================================================================
// Zero the sparse output region (standalone, side stream)
// ======================================================================
__global__ __launch_bounds__(256) void zero_kernel(float4* __restrict__ p, size_t n4) {
    const size_t stride = (size_t)gridDim.x * 256;
    const float4 z = make_float4(0.f, 0.f, 0.f, 0.f);
    for (size_t i = (size_t)blockIdx.x * 256 + threadIdx.x; i < n4; i += stride)
        p[i] = z;
}

// ======================================================================
// Approx encoder GEMM (bf16 HMMA) — R5/R8-proven config, verbatim.
// ======================================================================
__global__ __launch_bounds__(256) void enc_hmma_kernel(const float* __restrict__ bias,
                                                       __nv_bfloat16* __restrict__ C) {
    extern __shared__ __align__(1024) char smem[];   // 2 stages x 32KB
    const int tid = threadIdx.x;
    const int wid = tid >> 5, lane = tid & 31;
    const int bm = blockIdx.y * 128, bn = blockIdx.x * 128;
    const int wm = (wid >> 2) * 64, wn = (wid & 3) * 32;

    float acc[4][4][4];
#pragma unroll
    for (int i = 0; i < 4; i++)
#pragma unroll
        for (int j = 0; j < 4; j++)
#pragma unroll
            for (int q = 0; q < 4; q++) acc[i][j][q] = 0.f;

    const __nv_bfloat16* Abase = g_xb + (size_t)bm * K_D;
    const __nv_bfloat16* Bbase = g_wb + (size_t)bn * K_D;
    auto base_of = [&](int s) { return smem_u32(smem) + s * 32768; };

#define LOAD_TILE(s, kt)                                                          \
    {                                                                             \
        const uint32_t sa = base_of(s);                                           \
        const __nv_bfloat16* Ag = Abase + (kt) * 64;                              \
        const __nv_bfloat16* Bg = Bbase + (kt) * 64;                              \
        _Pragma("unroll")                                                         \
        for (int i = 0; i < 4; i++) {                                             \
            int u = tid + i * 256, row = u >> 3, kb = u & 7;                      \
            cp16(sa + SWZ(row * 128 + kb * 16), Ag + (size_t)row * K_D + kb * 8); \
        }                                                                         \
        _Pragma("unroll")                                                         \
        for (int i = 0; i < 4; i++) {                                             \
            int u = tid + i * 256, row = u >> 3, kb = u & 7;                      \
            cp16(sa + 16384 + SWZ(row * 128 + kb * 16), Bg + (size_t)row * K_D + kb * 8); \
        }                                                                         \
        cp_commit();                                                              \
    }

    LOAD_TILE(0, 0);
    int buf = 0;
    for (int kt = 0; kt < K_D / 64; ++kt) {
        if (kt + 1 < K_D / 64) { LOAD_TILE(buf ^ 1, kt + 1); cp_wait<1>(); }
        else cp_wait<0>();
        __syncthreads();

        const uint32_t sa = base_of(buf);
        const uint32_t sb = sa + 16384;
#pragma unroll
        for (int ks = 0; ks < 4; ks++) {
            uint32_t ra[4][4], rb[2][4];
#pragma unroll
            for (int mi = 0; mi < 4; mi++) {
                const int row = wm + mi * 16 + (lane & 15);
                const int koff = ks * 32 + ((lane >> 4) << 4);
                ldsm4(ra[mi][0], ra[mi][1], ra[mi][2], ra[mi][3],
                      sa + SWZ(row * 128 + koff));
            }
#pragma unroll
            for (int nb = 0; nb < 2; nb++) {
                const int nrow = wn + nb * 16 + ((lane >> 4) << 3) + (lane & 7);
                const int koff = ks * 32 + (((lane >> 3) & 1) << 4);
                ldsm4(rb[nb][0], rb[nb][1], rb[nb][2], rb[nb][3],
                      sb + SWZ(nrow * 128 + koff));
            }
#pragma unroll
            for (int mi = 0; mi < 4; mi++)
#pragma unroll
                for (int nj = 0; nj < 4; nj++)
                    mma16816(acc[mi][nj], ra[mi][0], ra[mi][1], ra[mi][2], ra[mi][3],
                             rb[nj >> 1][(nj & 1) * 2], rb[nj >> 1][(nj & 1) * 2 + 1]);
        }
        __syncthreads();
        buf ^= 1;
    }

    // epilogue: + bias -> bf16 store; per-(row, 32-col-chunk) max keys
    const int g = lane >> 2, t = lane & 3;
    const int chunk = (bn >> 5) + (wid & 3);
#pragma unroll
    for (int mi = 0; mi < 4; mi++) {
        const int r0 = bm + wm + mi * 16 + g;
        unsigned k0 = 0u, k1 = 0u;
#pragma unroll
        for (int nj = 0; nj < 4; nj++) {
            const int col = bn + wn + nj * 8 + 2 * t;
            const float2 bv = *(const float2*)(bias + col);
            __nv_bfloat162 p0 = __floats2bfloat162_rn(acc[mi][nj][0] + bv.x,
                                                      acc[mi][nj][1] + bv.y);
            __nv_bfloat162 p1 = __floats2bfloat162_rn(acc[mi][nj][2] + bv.x,
                                                      acc[mi][nj][3] + bv.y);
            const uint32_t u0 = *(uint32_t*)&p0, u1 = *(uint32_t*)&p1;
            k0 = max(k0, max(u0 & 0x7FFFu, (u0 >> 16) & 0x7FFFu));
            k1 = max(k1, max(u1 & 0x7FFFu, (u1 >> 16) & 0x7FFFu));
            *(__nv_bfloat162*)(C + (size_t)r0 * N_H + col) = p0;
            *(__nv_bfloat162*)(C + (size_t)(r0 + 8) * N_H + col) = p1;
        }
        k0 = max(k0, __shfl_xor_sync(0xffffffffu, k0, 1));
        k0 = max(k0, __shfl_xor_sync(0xffffffffu, k0, 2));
        k1 = max(k1, __shfl_xor_sync(0xffffffffu, k1, 1));
        k1 = max(k1, __shfl_xor_sync(0xffffffffu, k1, 2));
        if (t == 0) {
            g_cmax[(size_t)r0 * NCHUNKS + chunk] = (unsigned short)k0;
            g_cmax[(size_t)(r0 + 8) * NCHUNKS + chunk] = (unsigned short)k1;
        }
    }
}

// ======================================================================
// Transpose W_dec [1024, 16384] -> g_Wt [16384, 1024]
// ======================================================================
__global__ void transpose_kernel(const float* __restrict__ W) {
    __shared__ float t[32][33];
    const int h0 = blockIdx.x * 32;
    const int d0 = blockIdx.y * 32;
    const int tx = threadIdx.x, ty = threadIdx.y;
#pragma unroll
    for (int i = 0; i < 32; i += 8)
        t[ty + i][tx] = W[(size_t)(d0 + ty + i) * N_H + h0 + tx];
    __syncthreads();
#pragma unroll
    for (int i = 0; i < 32; i += 8)
        g_Wt[(size_t)(h0 + ty + i) * K_D + d0 + tx] = t[tx][ty + i];
}

// ======================================================================
// S1: per-row threshold + candidate emission (R14-proven, full grid).
// ======================================================================
__global__ __launch_bounds__(256) void select1_kernel() {
    __shared__ unsigned short scmax[NCHUNKS];    // 1KB
    __shared__ unsigned short achunk[NCHUNKS];   // 1KB
    __shared__ unsigned s_na, s_emit, s_thrkey;

    const int tid = threadIdx.x;
    const int row = blockIdx.x;
    const int wid = tid >> 5, lane = tid & 31;

    if (tid == 0) { s_na = 0u; s_emit = 0u; }
    ((uint32_t*)scmax)[tid] = ((const uint32_t*)(g_cmax + (size_t)row * NCHUNKS))[tid];
    __syncthreads();

    if (wid == 0) {
        const uint32_t* sc32 = (const uint32_t*)scmax;
        unsigned mx = 0u;
        for (int i = 0; i < 8; i++) {
            const uint32_t u = sc32[lane + 32 * i];
            mx = max(mx, max(u & 0xFFFFu, u >> 16));
        }
#pragma unroll
        for (int o = 16; o; o >>= 1) mx = max(mx, __shfl_xor_sync(0xffffffffu, mx, o));
        unsigned lo = 0u, hi = mx;
        for (int it = 0; it < 15; ++it) {
            if (lo >= hi) break;
            const unsigned mid = lo + ((hi - lo + 1) >> 1);
            unsigned c = 0;
            for (int i = 0; i < 8; i++) {
                const uint32_t u = sc32[lane + 32 * i];
                c += ((u & 0xFFFFu) >= mid) + ((u >> 16) >= mid);
            }
#pragma unroll
            for (int o = 16; o; o >>= 1) c += __shfl_xor_sync(0xffffffffu, c, o);
            if (c >= (unsigned)KSEL) lo = mid; else hi = mid - 1;
        }
        const unsigned short tsub = (unsigned short)lo;
        float tsubf;
        { __nv_bfloat16 h = *(__nv_bfloat16*)&tsub; tsubf = __bfloat162float(h); }
        const float thrf = fmaxf(tsubf - (0.03125f + 0.015625f * tsubf), 0.f);
        unsigned thrkey;
        { __nv_bfloat16 h = __float2bfloat16_rz(thrf); thrkey = *(unsigned short*)&h; }
        if (lane == 0) { s_thrkey = thrkey; g_thr[row] = thrf; }
        for (int i = 0; i < 8; i++) {
            const uint32_t u = sc32[lane + 32 * i];
            if ((u & 0xFFFFu) >= thrkey) {
                unsigned p = atomicAdd(&s_na, 1u);
                achunk[p] = (unsigned short)(2 * (lane + 32 * i));
            }
            if ((u >> 16) >= thrkey) {
                unsigned p = atomicAdd(&s_na, 1u);
                achunk[p] = (unsigned short)(2 * (lane + 32 * i) + 1);
            }
        }
    }
    __syncthreads();
    const unsigned thrkey = s_thrkey;
    const int na = (int)s_na;

    const uint32_t* erow = (const uint32_t*)(g_encbf + (size_t)row * N_H);
    for (int i = wid * 2; i < na; i += 16) {
        const int slot = i + (lane >> 4);
        if (slot < na) {
            const int c = achunk[slot];
            const uint32_t u = erow[c * 16 + (lane & 15)];
            const unsigned klo = u & 0x7FFFu, khi = (u >> 16) & 0x7FFFu;
            if (klo >= thrkey) {
                unsigned p = atomicAdd(&s_emit, 1u);
                if (p < CANDCAP) g_cand[(size_t)row * CANDCAP + p] = c * 32 + 2 * (lane & 15);
            }
            if (khi >= thrkey) {
                unsigned p = atomicAdd(&s_emit, 1u);
                if (p < CANDCAP) g_cand[(size_t)row * CANDCAP + p] = c * 32 + 2 * (lane & 15) + 1;
            }
        }
    }
    __syncthreads();
    if (tid == 0) g_ccnt[row] = (int)min(s_emit, (unsigned)CANDCAP);
}

// ======================================================================
// S2: exact fp32 recompute of all candidates (R14-proven, full grid).
// ======================================================================
__global__ __launch_bounds__(256) void recompute_kernel(const float* __restrict__ x,
                                                        const float* __restrict__ W,
                                                        const float* __restrict__ benc) {
    __shared__ float sx[K_D];
    const int tid = threadIdx.x;
    const int row = blockIdx.x;
    const int wid = tid >> 5, lane = tid & 31;

    ((float4*)sx)[tid] = ((const float4*)(x + (size_t)row * K_D))[tid];
    __syncthreads();

    const int cn = g_ccnt[row];
    const float4* sx4 = (const float4*)sx;
    for (int c = wid; c < cn; c += 8) {
        const int j = g_cand[(size_t)row * CANDCAP + c];
        const float4* wr = (const float4*)(W + (size_t)j * K_D);
        float s = 0.f;
#pragma unroll
        for (int i = 0; i < 8; i++) {
            const float4 w4 = wr[lane + i * 32];
            const float4 x4 = sx4[lane + i * 32];
            s += w4.x * x4.x + w4.y * x4.y + w4.z * x4.z + w4.w * x4.w;
        }
#pragma unroll
        for (int o = 16; o; o >>= 1) s += __shfl_xor_sync(0xffffffffu, s, o);
        if (lane == 0) g_cval[(size_t)row * CANDCAP + c] = s + benc[j];
    }
}

// ======================================================================
// D3 (merged S3+decode): exact top-32 bisection among candidates +
// scatter into pre-zeroed sparse row + decode the row from g_Wt.
// ======================================================================
__global__ __launch_bounds__(256) void decode3_kernel(const float* __restrict__ bdec,
                                                      float* __restrict__ sparse,
                                                      float* __restrict__ decoded) {
    __shared__ float cval[CANDCAP];
    __shared__ int   cidx[CANDCAP];
    __shared__ int   s_sidx[KSEL];
    __shared__ float s_sval[KSEL];
    __shared__ unsigned s_sel;

    const int tid = threadIdx.x;
    const int row = blockIdx.x;
    const int wid = tid >> 5, lane = tid & 31;
    const int cn = g_ccnt[row];

    if (tid == 0) s_sel = 0u;
    if (tid < KSEL) { s_sidx[tid] = 0; s_sval[tid] = 0.f; }
    for (int i = tid; i < cn; i += 256) {
        cval[i] = g_cval[(size_t)row * CANDCAP + i];
        cidx[i] = g_cand[(size_t)row * CANDCAP + i];
    }
    __syncthreads();

    if (wid == 0) {
        unsigned mx = 0u;
        for (int i = lane; i < cn; i += 32)
            mx = max(mx, __float_as_uint(fabsf(cval[i])));
#pragma unroll
        for (int o = 16; o; o >>= 1) mx = max(mx, __shfl_xor_sync(0xffffffffu, mx, o));
        unsigned lo = __float_as_uint(g_thr[row]), hi = mx;
        for (int it = 0; it < 32; ++it) {
            if (lo >= hi) break;
            const unsigned mid = lo + ((hi - lo + 1) >> 1);
            unsigned c = 0;
            for (int i = lane; i < cn; i += 32)
                c += (__float_as_uint(fabsf(cval[i])) >= mid);
#pragma unroll
            for (int o = 16; o; o >>= 1) c += __shfl_xor_sync(0xffffffffu, c, o);
            if (c >= (unsigned)KSEL) lo = mid; else hi = mid - 1;
        }
        const unsigned T = lo;
        for (int i = lane; i < cn; i += 32) {
            const float vv = cval[i];
            if (__float_as_uint(fabsf(vv)) >= T) {
                unsigned p = atomicAdd(&s_sel, 1u);
                if (p < (unsigned)KSEL) { s_sidx[p] = cidx[i]; s_sval[p] = vv; }
            }
        }
    }
    __syncthreads();

    // scatter winners (row pre-zeroed by zero_kernel)
    if (tid < KSEL && tid < (int)min(s_sel, (unsigned)KSEL))
        sparse[(size_t)row * N_H + s_sidx[tid]] = s_sval[tid];

    // decode row
    {
        const float4* Wt4 = (const float4*)g_Wt;
        float4 acc = ((const float4*)bdec)[tid];
#pragma unroll 8
        for (int j = 0; j < KSEL; j++) {
            const float4 w = Wt4[(size_t)s_sidx[j] * (K_D / 4) + tid];
            const float s = s_sval[j];
            acc.x += s * w.x; acc.y += s * w.y; acc.z += s * w.z; acc.w += s * w.w;
        }
        ((float4*)(decoded + (size_t)row * K_D))[tid] = acc;
    }
}

// ======================================================================
extern "C" void kernel_launch(void* const* d_in, const int* in_sizes, int n_in,
                              void* d_out, int out_size) {
    const float* x     = (const float*)d_in[0];
    const float* W_enc = (const float*)d_in[1];
    const float* b_enc = (const float*)d_in[2];
    const float* W_dec = (const float*)d_in[3];
    const float* b_dec = (const float*)d_in[4];

    float* out = (float*)d_out;
    float* sparse  = out;
    float* decoded = out + (size_t)M_B * N_H;

    __nv_bfloat16 *xb = nullptr, *wb = nullptr, *encbf = nullptr;
    cudaGetSymbolAddress((void**)&xb, g_xb);
    cudaGetSymbolAddress((void**)&wb, g_wb);
    cudaGetSymbolAddress((void**)&encbf, g_encbf);

    // one-time host-side handles (created on the uncaptured correctness call)
    static cudaStream_t s_side = nullptr;
    static cudaEvent_t  s_ev0 = nullptr, s_ev1 = nullptr;
    if (s_side == nullptr) {
        cudaStreamCreateWithFlags(&s_side, cudaStreamNonBlocking);
        cudaEventCreateWithFlags(&s_ev0, cudaEventDisableTiming);
        cudaEventCreateWithFlags(&s_ev1, cudaEventDisableTiming);
        cudaFuncSetAttribute(enc_hmma_kernel,
                             cudaFuncAttributeMaxDynamicSharedMemorySize, 65536);
    }

    // fork side stream from the (captured) origin stream
    cudaEventRecord(s_ev0, 0);
    cudaStreamWaitEvent(s_side, s_ev0, 0);

    // side stream: W_dec transpose + zero-fill (DRAM-bound; hidden under GEMM)
    transpose_kernel<<<dim3(N_H / 32, K_D / 32), dim3(32, 8), 0, s_side>>>(W_dec);
    zero_kernel<<<8192, 256, 0, s_side>>>((float4*)sparse, (size_t)M_B * N_H / 4);
    cudaEventRecord(s_ev1, s_side);

    // main stream: bf16 conversions -> approx GEMM
    convert_kernel<<<(M_B * K_D / 4) / 256, 256>>>(x, xb);
    convert_kernel<<<(int)(((size_t)N_H * K_D / 4) / 256), 256>>>(W_enc, wb);
    enc_hmma_kernel<<<dim3(N_H / 128, M_B / 128), 256, 65536>>>(b_enc, encbf);

    // join, then R14-proven monolithic-grid tail with merged S3+decode
    cudaStreamWaitEvent(0, s_ev1, 0);
    select1_kernel<<<M_B, 256>>>();
    recompute_kernel<<<M_B, 256>>>(x, W_enc, b_enc);
    decode3_kernel<<<M_B, 256>>>(b_dec, sparse, decoded);
}

// round 17
// speedup vs baseline: 1.0614x; 1.0369x over previous
#include <cuda_runtime.h>
#include <cuda_bf16.h>
#include <cstdint>

#define M_B 4096
#define N_H 16384
#define K_D 1024
#define KSEL 32
#define NCHUNKS 512          // 16384 / 32 cols per chunk
#define CANDCAP 512

// ---------------- scratch (device globals; no allocation) ----------------
__device__ __nv_bfloat16 g_xb[(size_t)M_B * K_D];        // 8MB   x in bf16
__device__ __nv_bfloat16 g_wb[(size_t)N_H * K_D];        // 33MB  W_enc in bf16
__device__ __nv_bfloat16 g_encbf[(size_t)M_B * N_H];     // 134MB approx enc (bf16)
__device__ unsigned short g_cmax[(size_t)M_B * NCHUNKS]; // 4MB chunk max |bf16| keys
__device__ float g_Wt[(size_t)N_H * K_D];                // 64MB  W_dec^T
__device__ int   g_cand[(size_t)M_B * CANDCAP];          // 8MB candidate indices
__device__ float g_cval[(size_t)M_B * CANDCAP];          // 8MB candidate exact values
__device__ int   g_ccnt[M_B];
__device__ float g_thr[M_B];
__device__ int   g_topk_idx[M_B * KSEL];
__device__ float g_topk_val[M_B * KSEL];

// ======================= helpers =======================
__device__ __forceinline__ uint32_t smem_u32(const void* p) {
    uint32_t a;
    asm("{ .reg .u64 t; cvta.to.shared.u64 t, %1; cvt.u32.u64 %0, t; }" : "=r"(a) : "l"(p));
    return a;
}
__device__ __forceinline__ void cp16(uint32_t dst, const void* src) {
    asm volatile("cp.async.cg.shared.global [%0], [%1], 16;" :: "r"(dst), "l"(src) : "memory");
}
__device__ __forceinline__ void cp_commit() {
    asm volatile("cp.async.commit_group;" ::: "memory");
}
template <int N> __device__ __forceinline__ void cp_wait() {
    asm volatile("cp.async.wait_group %0;" :: "n"(N) : "memory");
}
__device__ __forceinline__ void ldsm4(uint32_t& r0, uint32_t& r1, uint32_t& r2,
                                      uint32_t& r3, uint32_t a) {
    asm volatile("ldmatrix.sync.aligned.m8n8.x4.shared.b16 {%0,%1,%2,%3}, [%4];"
                 : "=r"(r0), "=r"(r1), "=r"(r2), "=r"(r3) : "r"(a));
}
__device__ __forceinline__ void mma16816(float* d, uint32_t a0, uint32_t a1,
                                         uint32_t a2, uint32_t a3,
                                         uint32_t b0, uint32_t b1) {
    asm volatile("mma.sync.aligned.m16n8k16.row.col.f32.bf16.bf16.f32 "
                 "{%0,%1,%2,%3}, {%4,%5,%6,%7}, {%8,%9}, {%0,%1,%2,%3};"
                 : "+f"(d[0]), "+f"(d[1]), "+f"(d[2]), "+f"(d[3])
                 : "r"(a0), "r"(a1), "r"(a2), "r"(a3), "r"(b0), "r"(b1));
}
#define SWZ(off) ((off) ^ (((off) >> 3) & 0x70))

// ======================================================================
// fp32 -> bf16 conversion
// ======================================================================
__global__ __launch_bounds__(256) void convert_kernel(const float* __restrict__ src,
                                                      __nv_bfloat16* __restrict__ dst) {
    const size_t g = (size_t)blockIdx.x * 256 + threadIdx.x;
    const float4 v = ((const float4*)src)[g];
    __nv_bfloat162 lo = __floats2bfloat162_rn(v.x, v.y);
    __nv_bfloat162 hi = __floats2bfloat162_rn(v.z, v.w);
    uint32_t a = *(uint32_t*)&lo, b = *(uint32_t*)&hi;
    ((uint2*)dst)[g] = make_uint2(a, b);
}

// ======================================================================
// Zero the sparse output region (standalone, side stream)
// ======================================================================
__global__ __launch_bounds__(256) void zero_kernel(float4* __restrict__ p, size_t n4) {
    const size_t stride = (size_t)gridDim.x * 256;
    const float4 z = make_float4(0.f, 0.f, 0.f, 0.f);
    for (size_t i = (size_t)blockIdx.x * 256 + threadIdx.x; i < n4; i += stride)
        p[i] = z;
}

// ======================================================================
// Approx encoder GEMM (bf16 HMMA) — R5/R8-proven config, verbatim.
// ======================================================================
__global__ __launch_bounds__(256) void enc_hmma_kernel(const float* __restrict__ bias,
                                                       __nv_bfloat16* __restrict__ C) {
    extern __shared__ __align__(1024) char smem[];   // 2 stages x 32KB
    const int tid = threadIdx.x;
    const int wid = tid >> 5, lane = tid & 31;
    const int bm = blockIdx.y * 128, bn = blockIdx.x * 128;
    const int wm = (wid >> 2) * 64, wn = (wid & 3) * 32;

    float acc[4][4][4];
#pragma unroll
    for (int i = 0; i < 4; i++)
#pragma unroll
        for (int j = 0; j < 4; j++)
#pragma unroll
            for (int q = 0; q < 4; q++) acc[i][j][q] = 0.f;

    const __nv_bfloat16* Abase = g_xb + (size_t)bm * K_D;
    const __nv_bfloat16* Bbase = g_wb + (size_t)bn * K_D;
    auto base_of = [&](int s) { return smem_u32(smem) + s * 32768; };

#define LOAD_TILE(s, kt)                                                          \
    {                                                                             \
        const uint32_t sa = base_of(s);                                           \
        const __nv_bfloat16* Ag = Abase + (kt) * 64;                              \
        const __nv_bfloat16* Bg = Bbase + (kt) * 64;                              \
        _Pragma("unroll")                                                         \
        for (int i = 0; i < 4; i++) {                                             \
            int u = tid + i * 256, row = u >> 3, kb = u & 7;                      \
            cp16(sa + SWZ(row * 128 + kb * 16), Ag + (size_t)row * K_D + kb * 8); \
        }                                                                         \
        _Pragma("unroll")                                                         \
        for (int i = 0; i < 4; i++) {                                             \
            int u = tid + i * 256, row = u >> 3, kb = u & 7;                      \
            cp16(sa + 16384 + SWZ(row * 128 + kb * 16), Bg + (size_t)row * K_D + kb * 8); \
        }                                                                         \
        cp_commit();                                                              \
    }

    LOAD_TILE(0, 0);
    int buf = 0;
    for (int kt = 0; kt < K_D / 64; ++kt) {
        if (kt + 1 < K_D / 64) { LOAD_TILE(buf ^ 1, kt + 1); cp_wait<1>(); }
        else cp_wait<0>();
        __syncthreads();

        const uint32_t sa = base_of(buf);
        const uint32_t sb = sa + 16384;
#pragma unroll
        for (int ks = 0; ks < 4; ks++) {
            uint32_t ra[4][4], rb[2][4];
#pragma unroll
            for (int mi = 0; mi < 4; mi++) {
                const int row = wm + mi * 16 + (lane & 15);
                const int koff = ks * 32 + ((lane >> 4) << 4);
                ldsm4(ra[mi][0], ra[mi][1], ra[mi][2], ra[mi][3],
                      sa + SWZ(row * 128 + koff));
            }
#pragma unroll
            for (int nb = 0; nb < 2; nb++) {
                const int nrow = wn + nb * 16 + ((lane >> 4) << 3) + (lane & 7);
                const int koff = ks * 32 + (((lane >> 3) & 1) << 4);
                ldsm4(rb[nb][0], rb[nb][1], rb[nb][2], rb[nb][3],
                      sb + SWZ(nrow * 128 + koff));
            }
#pragma unroll
            for (int mi = 0; mi < 4; mi++)
#pragma unroll
                for (int nj = 0; nj < 4; nj++)
                    mma16816(acc[mi][nj], ra[mi][0], ra[mi][1], ra[mi][2], ra[mi][3],
                             rb[nj >> 1][(nj & 1) * 2], rb[nj >> 1][(nj & 1) * 2 + 1]);
        }
        __syncthreads();
        buf ^= 1;
    }

    // epilogue: + bias -> bf16 store; per-(row, 32-col-chunk) max keys
    const int g = lane >> 2, t = lane & 3;
    const int chunk = (bn >> 5) + (wid & 3);
#pragma unroll
    for (int mi = 0; mi < 4; mi++) {
        const int r0 = bm + wm + mi * 16 + g;
        unsigned k0 = 0u, k1 = 0u;
#pragma unroll
        for (int nj = 0; nj < 4; nj++) {
            const int col = bn + wn + nj * 8 + 2 * t;
            const float2 bv = *(const float2*)(bias + col);
            __nv_bfloat162 p0 = __floats2bfloat162_rn(acc[mi][nj][0] + bv.x,
                                                      acc[mi][nj][1] + bv.y);
            __nv_bfloat162 p1 = __floats2bfloat162_rn(acc[mi][nj][2] + bv.x,
                                                      acc[mi][nj][3] + bv.y);
            const uint32_t u0 = *(uint32_t*)&p0, u1 = *(uint32_t*)&p1;
            k0 = max(k0, max(u0 & 0x7FFFu, (u0 >> 16) & 0x7FFFu));
            k1 = max(k1, max(u1 & 0x7FFFu, (u1 >> 16) & 0x7FFFu));
            *(__nv_bfloat162*)(C + (size_t)r0 * N_H + col) = p0;
            *(__nv_bfloat162*)(C + (size_t)(r0 + 8) * N_H + col) = p1;
        }
        k0 = max(k0, __shfl_xor_sync(0xffffffffu, k0, 1));
        k0 = max(k0, __shfl_xor_sync(0xffffffffu, k0, 2));
        k1 = max(k1, __shfl_xor_sync(0xffffffffu, k1, 1));
        k1 = max(k1, __shfl_xor_sync(0xffffffffu, k1, 2));
        if (t == 0) {
            g_cmax[(size_t)r0 * NCHUNKS + chunk] = (unsigned short)k0;
            g_cmax[(size_t)(r0 + 8) * NCHUNKS + chunk] = (unsigned short)k1;
        }
    }
}

// ======================================================================
// Transpose W_dec [1024, 16384] -> g_Wt [16384, 1024]
// ======================================================================
__global__ void transpose_kernel(const float* __restrict__ W) {
    __shared__ float t[32][33];
    const int h0 = blockIdx.x * 32;
    const int d0 = blockIdx.y * 32;
    const int tx = threadIdx.x, ty = threadIdx.y;
#pragma unroll
    for (int i = 0; i < 32; i += 8)
        t[ty + i][tx] = W[(size_t)(d0 + ty + i) * N_H + h0 + tx];
    __syncthreads();
#pragma unroll
    for (int i = 0; i < 32; i += 8)
        g_Wt[(size_t)(h0 + ty + i) * K_D + d0 + tx] = t[tx][ty + i];
}

// ======================================================================
// S1: per-row threshold + candidate emission (R14-proven).
// ======================================================================
__global__ __launch_bounds__(256) void select1_kernel() {
    __shared__ unsigned short scmax[NCHUNKS];    // 1KB
    __shared__ unsigned short achunk[NCHUNKS];   // 1KB
    __shared__ unsigned s_na, s_emit, s_thrkey;

    const int tid = threadIdx.x;
    const int row = blockIdx.x;
    const int wid = tid >> 5, lane = tid & 31;

    if (tid == 0) { s_na = 0u; s_emit = 0u; }
    ((uint32_t*)scmax)[tid] = ((const uint32_t*)(g_cmax + (size_t)row * NCHUNKS))[tid];
    __syncthreads();

    if (wid == 0) {
        const uint32_t* sc32 = (const uint32_t*)scmax;
        unsigned mx = 0u;
        for (int i = 0; i < 8; i++) {
            const uint32_t u = sc32[lane + 32 * i];
            mx = max(mx, max(u & 0xFFFFu, u >> 16));
        }
#pragma unroll
        for (int o = 16; o; o >>= 1) mx = max(mx, __shfl_xor_sync(0xffffffffu, mx, o));
        unsigned lo = 0u, hi = mx;
        for (int it = 0; it < 15; ++it) {
            if (lo >= hi) break;
            const unsigned mid = lo + ((hi - lo + 1) >> 1);
            unsigned c = 0;
            for (int i = 0; i < 8; i++) {
                const uint32_t u = sc32[lane + 32 * i];
                c += ((u & 0xFFFFu) >= mid) + ((u >> 16) >= mid);
            }
#pragma unroll
            for (int o = 16; o; o >>= 1) c += __shfl_xor_sync(0xffffffffu, c, o);
            if (c >= (unsigned)KSEL) lo = mid; else hi = mid - 1;
        }
        const unsigned short tsub = (unsigned short)lo;
        float tsubf;
        { __nv_bfloat16 h = *(__nv_bfloat16*)&tsub; tsubf = __bfloat162float(h); }
        const float thrf = fmaxf(tsubf - (0.03125f + 0.015625f * tsubf), 0.f);
        unsigned thrkey;
        { __nv_bfloat16 h = __float2bfloat16_rz(thrf); thrkey = *(unsigned short*)&h; }
        if (lane == 0) { s_thrkey = thrkey; g_thr[row] = thrf; }
        for (int i = 0; i < 8; i++) {
            const uint32_t u = sc32[lane + 32 * i];
            if ((u & 0xFFFFu) >= thrkey) {
                unsigned p = atomicAdd(&s_na, 1u);
                achunk[p] = (unsigned short)(2 * (lane + 32 * i));
            }
            if ((u >> 16) >= thrkey) {
                unsigned p = atomicAdd(&s_na, 1u);
                achunk[p] = (unsigned short)(2 * (lane + 32 * i) + 1);
            }
        }
    }
    __syncthreads();
    const unsigned thrkey = s_thrkey;
    const int na = (int)s_na;

    const uint32_t* erow = (const uint32_t*)(g_encbf + (size_t)row * N_H);
    for (int i = wid * 2; i < na; i += 16) {
        const int slot = i + (lane >> 4);
        if (slot < na) {
            const int c = achunk[slot];
            const uint32_t u = erow[c * 16 + (lane & 15)];
            const unsigned klo = u & 0x7FFFu, khi = (u >> 16) & 0x7FFFu;
            if (klo >= thrkey) {
                unsigned p = atomicAdd(&s_emit, 1u);
                if (p < CANDCAP) g_cand[(size_t)row * CANDCAP + p] = c * 32 + 2 * (lane & 15);
            }
            if (khi >= thrkey) {
                unsigned p = atomicAdd(&s_emit, 1u);
                if (p < CANDCAP) g_cand[(size_t)row * CANDCAP + p] = c * 32 + 2 * (lane & 15) + 1;
            }
        }
    }
    __syncthreads();
    if (tid == 0) g_ccnt[row] = (int)min(s_emit, (unsigned)CANDCAP);
}

// ======================================================================
// S2: exact fp32 recompute of all candidates (R14-proven).
// ======================================================================
__global__ __launch_bounds__(256) void recompute_kernel(const float* __restrict__ x,
                                                        const float* __restrict__ W,
                                                        const float* __restrict__ benc) {
    __shared__ float sx[K_D];
    const int tid = threadIdx.x;
    const int row = blockIdx.x;
    const int wid = tid >> 5, lane = tid & 31;

    ((float4*)sx)[tid] = ((const float4*)(x + (size_t)row * K_D))[tid];
    __syncthreads();

    const int cn = g_ccnt[row];
    const float4* sx4 = (const float4*)sx;
    for (int c = wid; c < cn; c += 8) {
        const int j = g_cand[(size_t)row * CANDCAP + c];
        const float4* wr = (const float4*)(W + (size_t)j * K_D);
        float s = 0.f;
#pragma unroll
        for (int i = 0; i < 8; i++) {
            const float4 w4 = wr[lane + i * 32];
            const float4 x4 = sx4[lane + i * 32];
            s += w4.x * x4.x + w4.y * x4.y + w4.z * x4.z + w4.w * x4.w;
        }
#pragma unroll
        for (int o = 16; o; o >>= 1) s += __shfl_xor_sync(0xffffffffu, s, o);
        if (lane == 0) g_cval[(size_t)row * CANDCAP + c] = s + benc[j];
    }
}

// ======================================================================
// S3: per-row exact top-32 among candidates + scatter + (idx,val) emit.
// (R14-proven, 128 threads)
// ======================================================================
__global__ __launch_bounds__(128) void select3_kernel(float* __restrict__ sparse) {
    __shared__ float cval[CANDCAP];
    __shared__ int   cidx[CANDCAP];
    __shared__ unsigned s_sel;

    const int tid = threadIdx.x;
    const int row = blockIdx.x;
    const int wid = tid >> 5, lane = tid & 31;
    const int cn = g_ccnt[row];

    if (tid == 0) s_sel = 0u;
    if (tid < KSEL) {
        g_topk_idx[row * KSEL + tid] = 0;
        g_topk_val[row * KSEL + tid] = 0.f;
    }
    for (int i = tid; i < cn; i += 128) {
        cval[i] = g_cval[(size_t)row * CANDCAP + i];
        cidx[i] = g_cand[(size_t)row * CANDCAP + i];
    }
    __syncthreads();

    if (wid == 0) {
        unsigned mx = 0u;
        for (int i = lane; i < cn; i += 32)
            mx = max(mx, __float_as_uint(fabsf(cval[i])));
#pragma unroll
        for (int o = 16; o; o >>= 1) mx = max(mx, __shfl_xor_sync(0xffffffffu, mx, o));
        unsigned lo = __float_as_uint(g_thr[row]), hi = mx;
        for (int it = 0; it < 32; ++it) {
            if (lo >= hi) break;
            const unsigned mid = lo + ((hi - lo + 1) >> 1);
            unsigned c = 0;
            for (int i = lane; i < cn; i += 32)
                c += (__float_as_uint(fabsf(cval[i])) >= mid);
#pragma unroll
            for (int o = 16; o; o >>= 1) c += __shfl_xor_sync(0xffffffffu, c, o);
            if (c >= (unsigned)KSEL) lo = mid; else hi = mid - 1;
        }
        const unsigned T = lo;
        for (int i = lane; i < cn; i += 32) {
            const float vv = cval[i];
            if (__float_as_uint(fabsf(vv)) >= T) {
                unsigned p = atomicAdd(&s_sel, 1u);
                if (p < (unsigned)KSEL) {
                    const int jj = cidx[i];
                    sparse[(size_t)row * N_H + jj] = vv;   // row pre-zeroed
                    g_topk_idx[row * KSEL + p] = jj;
                    g_topk_val[row * KSEL + p] = vv;
                }
            }
        }
    }
}

// ======================================================================
// Decode: decoded[b,:] = sum_j val_j * Wt[idx_j,:] + b_dec  (R14-proven)
// ======================================================================
__global__ __launch_bounds__(256) void decode_kernel(const float* __restrict__ bdec,
                                                     float* __restrict__ out) {
    __shared__ int sidx[KSEL];
    __shared__ float sval[KSEL];
    const int row = blockIdx.x;
    const int tid = threadIdx.x;
    if (tid < KSEL) {
        sidx[tid] = g_topk_idx[row * KSEL + tid];
        sval[tid] = g_topk_val[row * KSEL + tid];
    }
    __syncthreads();

    const float4* Wt4 = (const float4*)g_Wt;
    float4 acc = make_float4(0.f, 0.f, 0.f, 0.f);
#pragma unroll 8
    for (int j = 0; j < KSEL; j++) {
        const float4 w = Wt4[(size_t)sidx[j] * (K_D / 4) + tid];
        const float s = sval[j];
        acc.x += s * w.x; acc.y += s * w.y; acc.z += s * w.z; acc.w += s * w.w;
    }
    const float4 b = ((const float4*)bdec)[tid];
    acc.x += b.x; acc.y += b.y; acc.z += b.z; acc.w += b.w;
    ((float4*)out)[(size_t)row * (K_D / 4) + tid] = acc;
}

// ======================================================================
extern "C" void kernel_launch(void* const* d_in, const int* in_sizes, int n_in,
                              void* d_out, int out_size) {
    const float* x     = (const float*)d_in[0];
    const float* W_enc = (const float*)d_in[1];
    const float* b_enc = (const float*)d_in[2];
    const float* W_dec = (const float*)d_in[3];
    const float* b_dec = (const float*)d_in[4];

    float* out = (float*)d_out;
    float* sparse  = out;
    float* decoded = out + (size_t)M_B * N_H;

    __nv_bfloat16 *xb = nullptr, *wb = nullptr, *encbf = nullptr;
    cudaGetSymbolAddress((void**)&xb, g_xb);
    cudaGetSymbolAddress((void**)&wb, g_wb);
    cudaGetSymbolAddress((void**)&encbf, g_encbf);

    // one-time host-side handles (created on the uncaptured correctness call)
    static cudaStream_t s_side = nullptr;
    static cudaEvent_t  s_ev0 = nullptr, s_evcx = nullptr, s_ev1 = nullptr;
    if (s_side == nullptr) {
        cudaStreamCreateWithFlags(&s_side, cudaStreamNonBlocking);
        cudaEventCreateWithFlags(&s_ev0, cudaEventDisableTiming);
        cudaEventCreateWithFlags(&s_evcx, cudaEventDisableTiming);
        cudaEventCreateWithFlags(&s_ev1, cudaEventDisableTiming);
        cudaFuncSetAttribute(enc_hmma_kernel,
                             cudaFuncAttributeMaxDynamicSharedMemorySize, 65536);
    }

    // fork side stream from the (captured) origin stream
    cudaEventRecord(s_ev0, 0);
    cudaStreamWaitEvent(s_side, s_ev0, 0);

    // side stream: x convert first (GEMM prerequisite, overlaps W convert),
    // then W_dec transpose + zero-fill (hidden under GEMM)
    convert_kernel<<<(M_B * K_D / 4) / 256, 256, 0, s_side>>>(x, xb);
    cudaEventRecord(s_evcx, s_side);
    transpose_kernel<<<dim3(N_H / 32, K_D / 32), dim3(32, 8), 0, s_side>>>(W_dec);
    zero_kernel<<<8192, 256, 0, s_side>>>((float4*)sparse, (size_t)M_B * N_H / 4);
    cudaEventRecord(s_ev1, s_side);

    // main stream: W convert (concurrent with side's x convert) -> GEMM
    convert_kernel<<<(int)(((size_t)N_H * K_D / 4) / 256), 256>>>(W_enc, wb);
    cudaStreamWaitEvent(0, s_evcx, 0);
    enc_hmma_kernel<<<dim3(N_H / 128, M_B / 128), 256, 65536>>>(b_enc, encbf);

    // join, then R14-proven phase-split tail
    cudaStreamWaitEvent(0, s_ev1, 0);
    select1_kernel<<<M_B, 256>>>();
    recompute_kernel<<<M_B, 256>>>(x, W_enc, b_enc);
    select3_kernel<<<M_B, 128>>>(sparse);
    decode_kernel<<<M_B, 256>>>(b_dec, decoded);
}